// round 9
// baseline (speedup 1.0000x reference)
#include <cuda_runtime.h>

#define NV   2000000
#define NC   2000
#define NE   16000
#define NREP 16        // replicas per cluster, padded to 32B stride

// Scratch (no cudaMalloc allowed).
// Replica r of cluster c lives at float4 index c*32 + r*2 (32B apart -> no
// two replicas share an L2 sector). 1 MB total.
__device__ float4       g_rsum[NC * NREP * 2];
__device__ unsigned int g_icnt[NC];

__device__ __forceinline__ void red_v4(float4* a, float x, float y, float z, float w) {
    asm volatile("red.global.add.v4.f32 [%0], {%1,%2,%3,%4};"
                 :: "l"(a), "f"(x), "f"(y), "f"(z), "f"(w) : "memory");
}
__device__ __forceinline__ void red_u32(unsigned int* a, unsigned int v) {
    asm volatile("red.global.add.u32 [%0], %1;" :: "l"(a), "r"(v) : "memory");
}
__device__ __forceinline__ void unpack2(unsigned long long v, float& a, float& b) {
    asm("mov.b64 {%0, %1}, %2;" : "=f"(a), "=f"(b) : "l"(v));
}
__device__ __forceinline__ void ffma2(unsigned long long& d,
                                      unsigned long long a, unsigned long long b) {
    asm("fma.rn.f32x2 %0, %1, %2, %0;" : "+l"(d) : "l"(a), "l"(b));
}

// ---------------------------------------------------------------------------
// Kernel 1: segment sum (R5 winner + sector-padded replicas).
//  - feature sums: replicated red.v4 to L2 (1 lane-op per voxel)
//  - counts: shared uint histogram flushed once per block with red.u32.
// ---------------------------------------------------------------------------
__global__ __launch_bounds__(256) void k_seg(const float* __restrict__ data,
                                             const int*   __restrict__ cid) {
    __shared__ unsigned int s_cnt[NC];   // 8 KB
    for (int i = threadIdx.x; i < NC; i += 256) s_cnt[i] = 0u;
    __syncthreads();

    const int rep2 = ((blockIdx.x * 8 + (threadIdx.x >> 5)) & (NREP - 1)) * 2;
    const int NG = NV / 4;
    const int stride = gridDim.x * 256;
#pragma unroll 2
    for (int g = blockIdx.x * 256 + threadIdx.x; g < NG; g += stride) {
        const float4* p = (const float4*)data + (size_t)g * 5;
        float4 q0 = __ldg(p + 0);
        float4 q1 = __ldg(p + 1);
        float4 q2 = __ldg(p + 2);
        float4 q3 = __ldg(p + 3);
        float4 q4 = __ldg(p + 4);
        int4 c = __ldg((const int4*)cid + g);

        // voxel layout: [d f0 f1 f2 f3] x4 -> features are cols 1..4
        red_v4(&g_rsum[c.x * (NREP * 2) + rep2], q0.y, q0.z, q0.w, q1.x);
        red_v4(&g_rsum[c.y * (NREP * 2) + rep2], q1.z, q1.w, q2.x, q2.y);
        red_v4(&g_rsum[c.z * (NREP * 2) + rep2], q2.w, q3.x, q3.y, q3.z);
        red_v4(&g_rsum[c.w * (NREP * 2) + rep2], q4.x, q4.y, q4.z, q4.w);

        atomicAdd(&s_cnt[c.x], 1u);
        atomicAdd(&s_cnt[c.y], 1u);
        atomicAdd(&s_cnt[c.z], 1u);
        atomicAdd(&s_cnt[c.w], 1u);
    }
    __syncthreads();

    for (int i = threadIdx.x; i < NC; i += 256) {
        unsigned int v = s_cnt[i];
        if (v) red_u32(&g_icnt[i], v);
    }
}

// ---------------------------------------------------------------------------
// Kernel 2: fused replica-reduce + gather + 2-layer MLP.
// 64 edges/block, 512 threads, grid=250, 100KB smem (2 CTAs/SM, 1 wave).
// Phase A writes h DUPLICATED: s_hdup[k][2e]=s_hdup[k][2e+1]=h[k][e], so
// Phase B's FFMA2 operands are aligned LDS.128 quad halves (zero pack MOVs):
//   per k per thread: 2x LDS.128 + 4x FFMA2 covering 2 edges x 4 outs.
// ---------------------------------------------------------------------------
__global__ __launch_bounds__(512) void k_mlp(const int*   __restrict__ eidx,
                                             const float* __restrict__ W1,
                                             const float* __restrict__ b1,
                                             const float* __restrict__ W2,
                                             const float* __restrict__ b2,
                                             float*       __restrict__ out) {
    extern __shared__ float sm[];
    float* s_W2   = sm;                 //  8192 floats [128][64]
    float* s_hdup = sm + 8192;          // 16384 floats [128][128] dup pairs
    float* s_W1   = sm + 24576;         //  512  floats [4][128]
    float* s_b1   = s_W1 + 512;         //  128
    float* s_b2   = s_b1 + 128;         //  64
    float* s_pool = s_b2 + 64;          //  320 floats [64][5]

    const int t = threadIdx.x;

    for (int i = t; i < 8192 / 4; i += 512)
        ((float4*)s_W2)[i] = ((const float4*)W2)[i];
    if (t < 128) ((float4*)s_W1)[t] = ((const float4*)W1)[t];
    if (t < 128) s_b1[t] = b1[t];
    if (t < 64)  s_b2[t] = b2[t];

    const int base = blockIdx.x * 64;

    // Fused gather: 8 threads per edge; thread q sums replicas 2q,2q+1 of
    // both endpoint clusters (4 pipelined LDG.128), 3-step shfl reduce.
    {
        int q = t & 7;
        int e = t >> 3;
        int eg = base + e;
        int a = __ldg(eidx + eg);
        int b = __ldg(eidx + NE + eg);

        const float4* ra = g_rsum + a * (NREP * 2) + q * 4;
        const float4* rb = g_rsum + b * (NREP * 2) + q * 4;
        float4 va0 = __ldg(ra + 0);
        float4 va1 = __ldg(ra + 2);
        float4 vb0 = __ldg(rb + 0);
        float4 vb1 = __ldg(rb + 2);
        float4 s = make_float4(va0.x + va1.x + vb0.x + vb1.x,
                               va0.y + va1.y + vb0.y + vb1.y,
                               va0.z + va1.z + vb0.z + vb1.z,
                               va0.w + va1.w + vb0.w + vb1.w);
#pragma unroll
        for (int off = 4; off > 0; off >>= 1) {
            s.x += __shfl_down_sync(0xffffffff, s.x, off);
            s.y += __shfl_down_sync(0xffffffff, s.y, off);
            s.z += __shfl_down_sync(0xffffffff, s.z, off);
            s.w += __shfl_down_sync(0xffffffff, s.w, off);
        }
        if (q == 0) {
            float cnt = (float)(__ldg(g_icnt + a) + __ldg(g_icnt + b));
            float inv = 1.f / fmaxf(cnt, 1.f);
            s_pool[e * 5 + 0] = s.x * inv;
            s_pool[e * 5 + 1] = s.y * inv;
            s_pool[e * 5 + 2] = s.z * inv;
            s_pool[e * 5 + 3] = s.w * inv;
        }
    }
    __syncthreads();

    // Phase A: e = t&63, k-range (t>>6)*16; duplicated store.
    {
        int e  = t & 63;
        int kq = (t >> 6) * 16;
        float p0 = s_pool[e * 5 + 0];
        float p1 = s_pool[e * 5 + 1];
        float p2 = s_pool[e * 5 + 2];
        float p3 = s_pool[e * 5 + 3];
#pragma unroll 4
        for (int j = 0; j < 16; j++) {
            int k = kq + j;
            float h = s_b1[k]
                    + p0 * s_W1[0 * 128 + k]
                    + p1 * s_W1[1 * 128 + k]
                    + p2 * s_W1[2 * 128 + k]
                    + p3 * s_W1[3 * 128 + k];
            h = fmaxf(h, 0.f);
            ((float2*)(s_hdup + k * 128 + e * 2))[0] = make_float2(h, h);
        }
    }
    __syncthreads();

    // Phase B: tx = out group (4 cols), ep = edge pair (2 edges). 512 threads.
    const int tx = t & 15;
    const int ep = t >> 4;                      // 0..31
    unsigned long long acc[2][2];               // [edge in pair][out pair]
    acc[0][0] = acc[0][1] = acc[1][0] = acc[1][1] = 0ull;

    const float4* hf4 = (const float4*)s_hdup;  // [128][32] quads
    const float4* wf4 = (const float4*)s_W2;    // [128][16] quads
#pragma unroll 8
    for (int k = 0; k < 128; k++) {
        float4 hd = hf4[k * 32 + ep];           // ((he0,he0),(he1,he1))
        float4 w  = wf4[k * 16 + tx];           // ((w0,w1),(w2,w3))
        const unsigned long long* hp = (const unsigned long long*)&hd;
        const unsigned long long* wp = (const unsigned long long*)&w;
        ffma2(acc[0][0], hp[0], wp[0]);
        ffma2(acc[0][1], hp[0], wp[1]);
        ffma2(acc[1][0], hp[1], wp[0]);
        ffma2(acc[1][1], hp[1], wp[1]);
    }

    float c0 = s_b2[tx * 4 + 0];
    float c1 = s_b2[tx * 4 + 1];
    float c2 = s_b2[tx * 4 + 2];
    float c3 = s_b2[tx * 4 + 3];
#pragma unroll
    for (int i = 0; i < 2; i++) {
        int e = base + ep * 2 + i;
        float a0, a1, a2, a3;
        unpack2(acc[i][0], a0, a1);
        unpack2(acc[i][1], a2, a3);
        float4 o = make_float4(a0 + c0, a1 + c1, a2 + c2, a3 + c3);
        ((float4*)out)[e * 16 + tx] = o;
    }
}

// ---------------------------------------------------------------------------
// Launch: memsets -> segment sum -> fused MLP (graph-capturable)
// ---------------------------------------------------------------------------
extern "C" void kernel_launch(void* const* d_in, const int* in_sizes, int n_in,
                              void* d_out, int out_size) {
    const float* data = (const float*)d_in[0];
    const int*   cid  = (const int*)  d_in[1];
    const int*   eidx = (const int*)  d_in[2];
    const float* W1   = (const float*)d_in[3];
    const float* b1   = (const float*)d_in[4];
    const float* W2   = (const float*)d_in[5];
    const float* b2   = (const float*)d_in[6];
    float*       out  = (float*)d_out;

    cudaFuncSetAttribute(k_mlp, cudaFuncAttributeMaxDynamicSharedMemorySize, 103424);

    void *p_rsum, *p_icnt;
    cudaGetSymbolAddress(&p_rsum, g_rsum);
    cudaGetSymbolAddress(&p_icnt, g_icnt);
    cudaMemsetAsync(p_rsum, 0, NC * NREP * 2 * sizeof(float4));
    cudaMemsetAsync(p_icnt, 0, NC * sizeof(unsigned int));

    k_seg<<<296, 256>>>(data, cid);
    k_mlp<<<NE / 64, 512, 103424>>>(eidx, W1, b1, W2, b2, out);
}